// round 14
// baseline (speedup 1.0000x reference)
#include <cuda_runtime.h>
#include <cuda_bf16.h>
#include <cstdint>

#define TLEN   128
#define HID    768
#define LHU    256
#define G4     1024
#define S_TOT  256
#define BATCH  8
#define NSENT  32
#define NCTA   128

typedef unsigned long long u64;

// ---------------- device scratch ----------------
__device__ float g_G    [2][(size_t)S_TOT * TLEN * G4];  // word pre-gates, gate-interleaved cols (4u+g)
__device__ float g_emb  [S_TOT * 2 * LHU];
__device__ float g_WshhX[2][LHU * LHU * 4];
__device__ float g_Gs   [2][S_TOT * G4];
__device__ float g_final[BATCH * 2 * LHU];
__device__ float g_wihX [2][G4 * HID];                   // word Wih rows permuted to 4u+g
__device__ float g_biasX[2][G4];
__device__ float g_WhhHi[2][G4 * LHU];                   // word Whh rows 4u+g, tf32-rounded
__device__ float g_hbuf [2][2][S_TOT * LHU];             // [parity][dir][seq*256+u]
__device__ int   g_grpbar[16];                           // per-(dir,mt) group barriers

// ---------------- helpers ----------------
__device__ __forceinline__ float sigf(float x) { return 1.f / (1.f + __expf(-x)); }
__device__ __forceinline__ float tanh_(float x) {
    float e = __expf(-2.f * fabsf(x));
    float r = (1.f - e) / (1.f + e);
    return copysignf(r, x);
}
__device__ __forceinline__ uint32_t tf32r(float f) {
    uint32_t o;
    asm("cvt.rna.tf32.f32 %0, %1;" : "=r"(o) : "f"(f));
    return o;
}
#define MMA_TF32(cc, a, b)                                              \
    asm volatile(                                                       \
        "mma.sync.aligned.m16n8k8.row.col.f32.tf32.tf32.f32 "           \
        "{%0,%1,%2,%3}, {%4,%5,%6,%7}, {%8,%9}, {%0,%1,%2,%3};"         \
        : "+f"((cc)[0]), "+f"((cc)[1]), "+f"((cc)[2]), "+f"((cc)[3])    \
        : "r"((a)[0]), "r"((a)[1]), "r"((a)[2]), "r"((a)[3]),           \
          "r"((b)[0]), "r"((b)[1]))
// ldmatrix x4: loads fragments for a 16-row x 8-b32-col tile (A) or two n8 tiles (B).
// Lane address: row = lane&15 (within 16-row block), b32-col offset = (lane>>4)*4.
__device__ __forceinline__ void ldm4(uint32_t* r, uint32_t saddr) {
    asm volatile("ldmatrix.sync.aligned.m8n8.x4.shared.b16 {%0,%1,%2,%3}, [%4];"
        : "=r"(r[0]), "=r"(r[1]), "=r"(r[2]), "=r"(r[3]) : "r"(saddr));
}

// ---------------- tf32 mma.sync GEMM, CTA 128x256, 8 warps (2M x 4N), warp 64x64 ----------------
#define GEMM_SMEM ((128 * 36 + 256 * 36) * 4)
__global__ void __launch_bounds__(256) mma_gemm(
    const float* __restrict__ A,
    const float* __restrict__ B0, const float* __restrict__ B1,
    const float* __restrict__ bias0, const float* __restrict__ bias1,
    float* __restrict__ C0, float* __restrict__ C1,
    int K)
{
    extern __shared__ uint32_t smq[];
    uint32_t* As = smq;
    uint32_t* Bs = smq + 128 * 36;

    int dir = blockIdx.x >> 2;
    int nt  = blockIdx.x & 3;
    int mt  = blockIdx.y;
    const float* Ap = A + (size_t)mt * 128 * K;
    const float* Bp = (dir ? B1 : B0) + (size_t)nt * 256 * K;
    const float* bi = (dir ? bias1 : bias0) + nt * 256;
    float* Cp = (dir ? C1 : C0) + (size_t)mt * 128 * G4 + nt * 256;

    int tid = threadIdx.x;
    int warp = tid >> 5, lane = tid & 31;
    int wm = warp & 1, wn = warp >> 1;
    int lr = lane >> 2, lc = lane & 3;

    uint32_t AsB = (uint32_t)__cvta_generic_to_shared(As);
    uint32_t BsB = (uint32_t)__cvta_generic_to_shared(Bs);
    uint32_t lmoff = ((lane & 15) * 36 + (lane >> 4) * 4) * 4;   // bytes

    float c[4][8][4];
#pragma unroll
    for (int mi = 0; mi < 4; mi++)
#pragma unroll
        for (int ni = 0; ni < 8; ni++)
#pragma unroll
            for (int j = 0; j < 4; j++) c[mi][ni][j] = 0.f;

    int nkt = K >> 5;
    for (int kt = 0; kt < nkt; kt++) {
        __syncthreads();
#pragma unroll
        for (int it = 0; it < 4; it++) {
            int i = tid + it * 256;
            int row = i >> 3, c4 = i & 7;
            float4 v = *(const float4*)(Ap + (size_t)row * K + kt * 32 + c4 * 4);
            uint32_t* d = As + row * 36 + c4 * 4;
            d[0] = tf32r(v.x); d[1] = tf32r(v.y); d[2] = tf32r(v.z); d[3] = tf32r(v.w);
        }
#pragma unroll
        for (int it = 0; it < 8; it++) {
            int i = tid + it * 256;
            int row = i >> 3, c4 = i & 7;
            float4 v = *(const float4*)(Bp + (size_t)row * K + kt * 32 + c4 * 4);
            uint32_t* d = Bs + row * 36 + c4 * 4;
            d[0] = tf32r(v.x); d[1] = tf32r(v.y); d[2] = tf32r(v.z); d[3] = tf32r(v.w);
        }
        __syncthreads();

#pragma unroll
        for (int kk = 0; kk < 4; kk++) {
            int k0 = kk * 8;
            uint32_t a[4][4];
#pragma unroll
            for (int mi = 0; mi < 4; mi++)
                ldm4(a[mi], AsB + ((wm * 64 + mi * 16) * 36 + k0) * 4 + lmoff);
            uint32_t b[8][2];
#pragma unroll
            for (int p = 0; p < 4; p++) {
                uint32_t bt[4];
                ldm4(bt, BsB + ((wn * 64 + p * 16) * 36 + k0) * 4 + lmoff);
                b[2 * p][0]     = bt[0];
                b[2 * p + 1][0] = bt[1];
                b[2 * p][1]     = bt[2];
                b[2 * p + 1][1] = bt[3];
            }
#pragma unroll
            for (int mi = 0; mi < 4; mi++)
#pragma unroll
                for (int ni = 0; ni < 8; ni++)
                    MMA_TF32(c[mi][ni], a[mi], b[ni]);
        }
    }

#pragma unroll
    for (int mi = 0; mi < 4; mi++) {
        int r0 = wm * 64 + mi * 16 + lr;
#pragma unroll
        for (int ni = 0; ni < 8; ni++) {
            int col = wn * 64 + ni * 8 + 2 * lc;
            float bx = bi[col], by = bi[col + 1];
            *(float2*)(Cp + (size_t)r0 * G4 + col) =
                make_float2(c[mi][ni][0] + bx, c[mi][ni][1] + by);
            *(float2*)(Cp + (size_t)(r0 + 8) * G4 + col) =
                make_float2(c[mi][ni][2] + bx, c[mi][ni][3] + by);
        }
    }
}

// ---------------- prep kernels ----------------
__global__ void prep_wihX(const float* __restrict__ wf, const float* __restrict__ wb) {
    int i = blockIdx.x * 256 + threadIdx.x;
    if (i >= G4 * HID) return;
    int row = i / HID, col = i - row * HID;
    int u = row >> 2, g = row & 3;
    int src = (g * LHU + u) * HID + col;
    g_wihX[0][i] = wf[src]; g_wihX[1][i] = wb[src];
}
__global__ void prep_misc(const float* __restrict__ bf, const float* __restrict__ bb,
                          const float* __restrict__ wf, const float* __restrict__ wb) {
    int i = blockIdx.x * 256 + threadIdx.x;
    if (i < G4) {
        int u = i >> 2, g = i & 3;
        g_biasX[0][i] = bf[g * LHU + u]; g_biasX[1][i] = bb[g * LHU + u];
    }
    if (i < G4 * LHU) {
        int row = i >> 8, k = i & 255;
        int u = row >> 2, g = row & 3;
        int src = (g * LHU + u) * LHU + k;
        g_WhhHi[0][i] = __uint_as_float(tf32r(wf[src]));
        g_WhhHi[1][i] = __uint_as_float(tf32r(wb[src]));
    }
    if (i < 2 * S_TOT * LHU) ((float*)g_hbuf)[i] = 0.f;
    if (i < 16) g_grpbar[i] = 0;
}
__global__ void prep_sent(const float* __restrict__ wsf, const float* __restrict__ wsb) {
    int i = blockIdx.x * 256 + threadIdx.x;
    if (i >= LHU * LHU * 4) return;
    int g = i & 3, u = (i >> 2) & 255, k = i >> 10;
    int src = (g * LHU + u) * LHU + k;
    g_WshhX[0][i] = wsf[src]; g_WshhX[1][i] = wsb[src];
}

// ---------------- persistent tensorized word BiLSTM ----------------
#define WP_SMEM ((8 * 128 * 36 + 2 * 8 * 32 * 36) * 4)   // 221184
__global__ void __launch_bounds__(256) word_persist(const int* __restrict__ mask) {
    extern __shared__ uint32_t smw[];
    uint32_t* Bs  = smw;                  // 8 * 4608
    uint32_t* Ahi = smw + 8 * 4608;       // 8 * 1152
    uint32_t* Alo = Ahi + 8 * 1152;
    float*    red = (float*)Ahi;          // overlay

    int cta = blockIdx.x;
    int dir = cta >> 6;
    int mt  = (cta >> 3) & 7;
    int nt  = cta & 7;
    int gid = cta >> 3;
    int tid = threadIdx.x;
    int w   = tid >> 5, lane = tid & 31;
    int wn  = w & 3, kh = w >> 2;
    int lr  = lane >> 2, lc = lane & 3;
    int odd = lc & 1;

    uint32_t AhiB = (uint32_t)__cvta_generic_to_shared(Ahi);
    uint32_t AloB = (uint32_t)__cvta_generic_to_shared(Alo);
    uint32_t BsB  = (uint32_t)__cvta_generic_to_shared(Bs);
    uint32_t lmoff = ((lane & 15) * 36 + (lane >> 4) * 4) * 4;

    // stage W slice once
    const float* Bsrc = g_WhhHi[dir] + (size_t)(nt * 128) * LHU;
#pragma unroll 4
    for (int i = tid; i < 128 * 64; i += 256) {
        int r = i >> 6, c4 = i & 63;
        float4 v = *(const float4*)(Bsrc + r * 256 + c4 * 4);
        int k = c4 * 4, ch = k >> 5, kin = k & 31;
        *(float4*)(Bs + ch * 4608 + r * 36 + kin) = v;
    }

    // epilogue-thread constants and state (warps 0-3 only)
    int      seqE[2];
    int      uE = nt * 32 + wn * 8 + (lc >> 1);
    float    cntE[2];
    uint32_t mb[2][4];
    float    c8[2][4], pool8[2][4];
    float4   Gpre[2][4];
#pragma unroll
    for (int mi = 0; mi < 2; mi++)
#pragma unroll
        for (int ni = 0; ni < 4; ni++) { c8[mi][ni] = 0.f; pool8[mi][ni] = 0.f; }
    if (kh == 0) {
#pragma unroll
        for (int mi = 0; mi < 2; mi++) {
            int seq = mt * 32 + mi * 16 + lr + (odd ? 8 : 0);
            seqE[mi] = seq;
            uint32_t b0 = 0, b1 = 0, b2 = 0, b3 = 0;
            for (int j = 0; j < 32; j++) {
                b0 |= (uint32_t)(mask[seq * TLEN + j]      != 0) << j;
                b1 |= (uint32_t)(mask[seq * TLEN + 32 + j] != 0) << j;
                b2 |= (uint32_t)(mask[seq * TLEN + 64 + j] != 0) << j;
                b3 |= (uint32_t)(mask[seq * TLEN + 96 + j] != 0) << j;
            }
            mb[mi][0] = b0; mb[mi][1] = b1; mb[mi][2] = b2; mb[mi][3] = b3;
            cntE[mi] = (float)(__popc(b0) + __popc(b1) + __popc(b2) + __popc(b3));
        }
    }
    __syncthreads();

    const float* Gd = g_G[dir];
    if (kh == 0) {
        int t0 = dir ? (TLEN - 1) : 0;
#pragma unroll
        for (int mi = 0; mi < 2; mi++)
#pragma unroll
            for (int ni = 0; ni < 4; ni++)
                Gpre[mi][ni] = *(const float4*)(Gd + ((size_t)seqE[mi] * TLEN + t0) * G4 + 4 * (uE + 2 * ni));
    }

    for (int step = 0; step < TLEN; step++) {
        int t = dir ? (TLEN - 1 - step) : step;
        const float* hcur  = g_hbuf[step & 1][dir];
        float*       hnext = g_hbuf[(step + 1) & 1][dir];

        // stage A: h rows mt*32..+32, all 256 k, hi/lo split
#pragma unroll
        for (int it = 0; it < 8; it++) {
            int i = tid + it * 256;
            int r = i >> 6, c4 = i & 63;
            float4 v = *(const float4*)(hcur + (size_t)(mt * 32 + r) * LHU + c4 * 4);
            int k = c4 * 4, ch = k >> 5, kin = k & 31;
            uint32_t hx = tf32r(v.x), hy = tf32r(v.y), hz = tf32r(v.z), hw = tf32r(v.w);
            uint32_t* dh = Ahi + ch * 1152 + r * 36 + kin;
            dh[0] = hx; dh[1] = hy; dh[2] = hz; dh[3] = hw;
            uint32_t* dl = Alo + ch * 1152 + r * 36 + kin;
            dl[0] = tf32r(v.x - __uint_as_float(hx));
            dl[1] = tf32r(v.y - __uint_as_float(hy));
            dl[2] = tf32r(v.z - __uint_as_float(hz));
            dl[3] = tf32r(v.w - __uint_as_float(hw));
        }
        __syncthreads();

        float acc[2][4][4];
#pragma unroll
        for (int mi = 0; mi < 2; mi++)
#pragma unroll
            for (int ni = 0; ni < 4; ni++)
#pragma unroll
                for (int j = 0; j < 4; j++) acc[mi][ni][j] = 0.f;

#pragma unroll
        for (int ccn = 0; ccn < 4; ccn++) {
            int ch = kh * 4 + ccn;
            uint32_t Ahc = AhiB + (ch * 1152) * 4;
            uint32_t Alc = AloB + (ch * 1152) * 4;
            uint32_t Bc  = BsB  + (ch * 4608 + wn * 32 * 36) * 4;
#pragma unroll
            for (int kk = 0; kk < 4; kk++) {
                int k0b = kk * 8 * 4;   // bytes
                uint32_t aH[2][4], aL[2][4], b[4][2];
                ldm4(aH[0], Ahc + k0b + lmoff);
                ldm4(aH[1], Ahc + 16 * 36 * 4 + k0b + lmoff);
                ldm4(aL[0], Alc + k0b + lmoff);
                ldm4(aL[1], Alc + 16 * 36 * 4 + k0b + lmoff);
                {
                    uint32_t bt[4];
                    ldm4(bt, Bc + k0b + lmoff);
                    b[0][0] = bt[0]; b[1][0] = bt[1]; b[0][1] = bt[2]; b[1][1] = bt[3];
                    ldm4(bt, Bc + 16 * 36 * 4 + k0b + lmoff);
                    b[2][0] = bt[0]; b[3][0] = bt[1]; b[2][1] = bt[2]; b[3][1] = bt[3];
                }
#pragma unroll
                for (int mi = 0; mi < 2; mi++)
#pragma unroll
                    for (int ni = 0; ni < 4; ni++) {
                        MMA_TF32(acc[mi][ni], aH[mi], b[ni]);
                        MMA_TF32(acc[mi][ni], aL[mi], b[ni]);
                    }
            }
        }
        __syncthreads();

        if (kh == 1) {
            float* rp = red + (tid - 128) * 32;
            int ii = 0;
#pragma unroll
            for (int mi = 0; mi < 2; mi++)
#pragma unroll
                for (int ni = 0; ni < 4; ni++)
#pragma unroll
                    for (int j = 0; j < 4; j++) rp[ii++] = acc[mi][ni][j];
        }
        __syncthreads();

        if (kh == 0) {
            const float* rp = red + tid * 32;
            int ii = 0;
#pragma unroll
            for (int mi = 0; mi < 2; mi++)
#pragma unroll
                for (int ni = 0; ni < 4; ni++)
#pragma unroll
                    for (int j = 0; j < 4; j++) acc[mi][ni][j] += rp[ii++];

#pragma unroll
            for (int mi = 0; mi < 2; mi++) {
                float mk = (float)((mb[mi][t >> 5] >> (t & 31)) & 1u);
                int seq = seqE[mi];
#pragma unroll
                for (int ni = 0; ni < 4; ni++) {
                    float x0 = acc[mi][ni][0], x1 = acc[mi][ni][1];
                    float x2 = acc[mi][ni][2], x3 = acc[mi][ni][3];
                    float r0 = __shfl_xor_sync(0xffffffff, x0, 1);
                    float r1 = __shfl_xor_sync(0xffffffff, x1, 1);
                    float r2 = __shfl_xor_sync(0xffffffff, x2, 1);
                    float r3 = __shfl_xor_sync(0xffffffff, x3, 1);
                    float gi, gf, gg, go;
                    if (!odd) { gi = x0; gf = x1; gg = r0; go = r1; }
                    else      { gi = r2; gf = r3; gg = x2; go = x3; }
                    float4 Gv = Gpre[mi][ni];
                    float iv = sigf(gi + Gv.x);
                    float fv = sigf(gf + Gv.y);
                    float gv = tanh_(gg + Gv.z);
                    float ov = sigf(go + Gv.w);
                    float cc2 = fv * c8[mi][ni] + iv * gv;
                    c8[mi][ni] = cc2;
                    float hn = ov * tanh_(cc2);
                    pool8[mi][ni] += mk * hn;
                    hnext[seq * LHU + uE + 2 * ni] = hn;
                }
            }
            if (step + 1 < TLEN) {
                int t2 = dir ? (TLEN - 2 - step) : (step + 1);
#pragma unroll
                for (int mi = 0; mi < 2; mi++)
#pragma unroll
                    for (int ni = 0; ni < 4; ni++)
                        Gpre[mi][ni] = *(const float4*)(Gd + ((size_t)seqE[mi] * TLEN + t2) * G4 + 4 * (uE + 2 * ni));
            }
        }

        if (step != TLEN - 1) {
            __threadfence();
            __syncthreads();
            if (tid == 0) {
                atomicAdd(&g_grpbar[gid], 1);
                int target = (step + 1) * 8;
                while (*((volatile int*)&g_grpbar[gid]) < target) { }
            }
            __syncthreads();
            __threadfence();
        }
    }

    if (kh == 0) {
#pragma unroll
        for (int mi = 0; mi < 2; mi++)
#pragma unroll
            for (int ni = 0; ni < 4; ni++) {
                int seq = seqE[mi];
                float cnt = cntE[mi];
                g_emb[seq * (2 * LHU) + dir * LHU + uE + 2 * ni] =
                    (cnt > 0.f) ? (pool8[mi][ni] / cnt) : 0.f;
            }
    }
}

// ---------------- sentence-level LSTM (fwd scan + bwd single step) ----------------
__device__ __forceinline__ u64 pack2(float lo, float hi) {
    u64 r;
    asm("mov.b64 %0, {%1, %2};" : "=l"(r) : "r"(__float_as_uint(lo)), "r"(__float_as_uint(hi)));
    return r;
}
__device__ __forceinline__ u64 dup2(float x) { return pack2(x, x); }
__device__ __forceinline__ void fma2(u64& a, u64 b, u64 c) {
    asm("fma.rn.f32x2 %0, %1, %2, %0;" : "+l"(a) : "l"(b), "l"(c));
}
__device__ __forceinline__ float2 unpack2(u64 v) {
    unsigned lo, hi;
    asm("mov.b64 {%0, %1}, %2;" : "=r"(lo), "=r"(hi) : "l"(v));
    return make_float2(__uint_as_float(lo), __uint_as_float(hi));
}
__global__ void __launch_bounds__(256) sent_lstm() {
    int b = blockIdx.x, u = threadIdx.x;
    __shared__ float h[LHU];
    h[u] = 0.f;
    float c = 0.f;
    __syncthreads();

    const ulonglong2* W2 = (const ulonglong2*)g_WshhX[0];
    for (int t = 0; t < NSENT; t++) {
        const float* gp = g_Gs[0] + (size_t)(b * NSENT + t) * G4;
        u64 aif = pack2(gp[u],           gp[LHU + u]);
        u64 ago = pack2(gp[2 * LHU + u], gp[3 * LHU + u]);
#pragma unroll 8
        for (int k = 0; k < LHU; k++) {
            ulonglong2 w = W2[k * LHU + u];
            u64 hd = dup2(h[k]);
            fma2(aif, w.x, hd);
            fma2(ago, w.y, hd);
        }
        float2 v1 = unpack2(aif), v2 = unpack2(ago);
        float cc = sigf(v1.y) * c + sigf(v1.x) * tanh_(v2.x);
        c = cc;
        float hn = sigf(v2.y) * tanh_(cc);
        __syncthreads();
        h[u] = hn;
        __syncthreads();
    }
    g_final[b * 2 * LHU + u] = h[u];

    const float* gp = g_Gs[1] + (size_t)(b * NSENT + NSENT - 1) * G4;
    float cc = sigf(gp[u]) * tanh_(gp[2 * LHU + u]);
    g_final[b * 2 * LHU + LHU + u] = sigf(gp[3 * LHU + u]) * tanh_(cc);
}

// ---------------- classifier ----------------
__global__ void classify(const float* __restrict__ cw, const float* __restrict__ cb,
                         float* __restrict__ out) {
    int tid = threadIdx.x;
    if (tid >= 32) return;
    int b = tid >> 2, cc = tid & 3;
    float s = cb[cc];
    for (int k = 0; k < 2 * LHU; k++)
        s += g_final[b * 2 * LHU + k] * cw[cc * 2 * LHU + k];
    out[b * 4 + cc] = s;
}

// ---------------- launch ----------------
extern "C" void kernel_launch(void* const* d_in, const int* in_sizes, int n_in,
                              void* d_out, int out_size) {
    const float* hidden  = (const float*)d_in[0];
    const int*   amask   = (const int*)  d_in[1];
    const float* wl_ih_f = (const float*)d_in[2];
    const float* wl_hh_f = (const float*)d_in[3];
    const float* wl_b_f  = (const float*)d_in[4];
    const float* wl_ih_b = (const float*)d_in[5];
    const float* wl_hh_b = (const float*)d_in[6];
    const float* wl_b_b  = (const float*)d_in[7];
    const float* ws_ih_f = (const float*)d_in[8];
    const float* ws_hh_f = (const float*)d_in[9];
    const float* ws_b_f  = (const float*)d_in[10];
    const float* ws_ih_b = (const float*)d_in[11];
    const float* ws_hh_b = (const float*)d_in[12];
    const float* ws_b_b  = (const float*)d_in[13];
    const float* cls_w   = (const float*)d_in[14];
    const float* cls_b   = (const float*)d_in[15];
    float* out = (float*)d_out;

    float *G0, *Gs0, *emb, *wihX0, *biasX0;
    cudaGetSymbolAddress((void**)&G0,     g_G);
    cudaGetSymbolAddress((void**)&Gs0,    g_Gs);
    cudaGetSymbolAddress((void**)&emb,    g_emb);
    cudaGetSymbolAddress((void**)&wihX0,  g_wihX);
    cudaGetSymbolAddress((void**)&biasX0, g_biasX);
    float* G1     = G0    + (size_t)S_TOT * TLEN * G4;
    float* Gs1    = Gs0   + (size_t)S_TOT * G4;
    float* wihX1  = wihX0 + (size_t)G4 * HID;
    float* biasX1 = biasX0 + G4;

    cudaFuncSetAttribute(mma_gemm,     cudaFuncAttributeMaxDynamicSharedMemorySize, GEMM_SMEM);
    cudaFuncSetAttribute(word_persist, cudaFuncAttributeMaxDynamicSharedMemorySize, WP_SMEM);

    // #1, #2: prep
    prep_wihX<<<(G4 * HID + 255) / 256, 256>>>(wl_ih_f, wl_ih_b);
    prep_misc<<<(G4 * LHU + 255) / 256, 256>>>(wl_b_f, wl_b_b, wl_hh_f, wl_hh_b);
    // #3: word pre-gates (interleaved cols)
    mma_gemm<<<dim3(8, (S_TOT * TLEN) / 128), 256, GEMM_SMEM>>>(
        hidden, wihX0, wihX1, biasX0, biasX1, G0, G1, HID);
    // #4: persistent tensorized word BiLSTM (profiled)
    word_persist<<<NCTA, 256, WP_SMEM>>>(amask);
    // #5-#8
    prep_sent<<<(LHU * LHU * 4 + 255) / 256, 256>>>(ws_hh_f, ws_hh_b);
    mma_gemm<<<dim3(8, S_TOT / 128), 256, GEMM_SMEM>>>(
        emb, ws_ih_f, ws_ih_b, ws_b_f, ws_b_b, Gs0, Gs1, 2 * LHU);
    sent_lstm<<<BATCH, 256>>>();
    classify<<<1, 32>>>(cls_w, cls_b, out);
}

// round 15
// speedup vs baseline: 1.7152x; 1.7152x over previous
#include <cuda_runtime.h>
#include <cuda_bf16.h>
#include <cstdint>

#define TLEN   128
#define HID    768
#define LHU    256
#define G4     1024
#define S_TOT  256
#define BATCH  8
#define NSENT  32
#define NCTA   128

typedef unsigned long long u64;

// ---------------- device scratch ----------------
__device__ float g_G    [2][(size_t)S_TOT * TLEN * G4];  // word pre-gates, gate-interleaved cols (4u+g)
__device__ float g_emb  [S_TOT * 2 * LHU];
__device__ float g_WshhX[2][LHU * LHU * 4];
__device__ float g_Gs   [2][S_TOT * G4];
__device__ float g_final[BATCH * 2 * LHU];
__device__ float g_wihX [2][G4 * HID];                   // word Wih rows permuted to 4u+g
__device__ float g_biasX[2][G4];
__device__ float g_WhhHi[2][G4 * LHU];                   // word Whh rows 4u+g, tf32-rounded
__device__ float g_hbuf [2][2][S_TOT * LHU];             // [parity][dir][seq*256+u]
__device__ int   g_grpbar[16];                           // per-(dir,mt) group barriers

// ---------------- helpers ----------------
__device__ __forceinline__ float sigf(float x) { return 1.f / (1.f + __expf(-x)); }
__device__ __forceinline__ float tanh_(float x) {
    float e = __expf(-2.f * fabsf(x));
    float r = (1.f - e) / (1.f + e);
    return copysignf(r, x);
}
__device__ __forceinline__ uint32_t tf32r(float f) {
    uint32_t o;
    asm("cvt.rna.tf32.f32 %0, %1;" : "=r"(o) : "f"(f));
    return o;
}
#define MMA_TF32(cc, a, b)                                              \
    asm volatile(                                                       \
        "mma.sync.aligned.m16n8k8.row.col.f32.tf32.tf32.f32 "           \
        "{%0,%1,%2,%3}, {%4,%5,%6,%7}, {%8,%9}, {%0,%1,%2,%3};"         \
        : "+f"((cc)[0]), "+f"((cc)[1]), "+f"((cc)[2]), "+f"((cc)[3])    \
        : "r"((a)[0]), "r"((a)[1]), "r"((a)[2]), "r"((a)[3]),           \
          "r"((b)[0]), "r"((b)[1]))

// ---------------- tf32 mma.sync GEMM, CTA 128x256, 8 warps (2M x 4N), warp 64x64 (R13 form) ----------------
#define GEMM_SMEM ((128 * 36 + 256 * 36) * 4)
__global__ void __launch_bounds__(256) mma_gemm(
    const float* __restrict__ A,
    const float* __restrict__ B0, const float* __restrict__ B1,
    const float* __restrict__ bias0, const float* __restrict__ bias1,
    float* __restrict__ C0, float* __restrict__ C1,
    int K)
{
    extern __shared__ uint32_t smq[];
    uint32_t* As = smq;
    uint32_t* Bs = smq + 128 * 36;

    int dir = blockIdx.x >> 2;
    int nt  = blockIdx.x & 3;
    int mt  = blockIdx.y;
    const float* Ap = A + (size_t)mt * 128 * K;
    const float* Bp = (dir ? B1 : B0) + (size_t)nt * 256 * K;
    const float* bi = (dir ? bias1 : bias0) + nt * 256;
    float* Cp = (dir ? C1 : C0) + (size_t)mt * 128 * G4 + nt * 256;

    int tid = threadIdx.x;
    int warp = tid >> 5, lane = tid & 31;
    int wm = warp & 1, wn = warp >> 1;
    int lr = lane >> 2, lc = lane & 3;

    float c[4][8][4];
#pragma unroll
    for (int mi = 0; mi < 4; mi++)
#pragma unroll
        for (int ni = 0; ni < 8; ni++)
#pragma unroll
            for (int j = 0; j < 4; j++) c[mi][ni][j] = 0.f;

    int nkt = K >> 5;
    for (int kt = 0; kt < nkt; kt++) {
        __syncthreads();
#pragma unroll
        for (int it = 0; it < 4; it++) {
            int i = tid + it * 256;
            int row = i >> 3, c4 = i & 7;
            float4 v = *(const float4*)(Ap + (size_t)row * K + kt * 32 + c4 * 4);
            uint32_t* d = As + row * 36 + c4 * 4;
            d[0] = tf32r(v.x); d[1] = tf32r(v.y); d[2] = tf32r(v.z); d[3] = tf32r(v.w);
        }
#pragma unroll
        for (int it = 0; it < 8; it++) {
            int i = tid + it * 256;
            int row = i >> 3, c4 = i & 7;
            float4 v = *(const float4*)(Bp + (size_t)row * K + kt * 32 + c4 * 4);
            uint32_t* d = Bs + row * 36 + c4 * 4;
            d[0] = tf32r(v.x); d[1] = tf32r(v.y); d[2] = tf32r(v.z); d[3] = tf32r(v.w);
        }
        __syncthreads();

#pragma unroll
        for (int kk = 0; kk < 4; kk++) {
            int k0 = kk * 8;
            uint32_t a[4][4];
#pragma unroll
            for (int mi = 0; mi < 4; mi++) {
                int r = wm * 64 + mi * 16 + lr;
                a[mi][0] = As[r * 36 + k0 + lc];
                a[mi][1] = As[(r + 8) * 36 + k0 + lc];
                a[mi][2] = As[r * 36 + k0 + lc + 4];
                a[mi][3] = As[(r + 8) * 36 + k0 + lc + 4];
            }
            uint32_t b[8][2];
#pragma unroll
            for (int ni = 0; ni < 8; ni++) {
                int n = wn * 64 + ni * 8 + lr;
                b[ni][0] = Bs[n * 36 + k0 + lc];
                b[ni][1] = Bs[n * 36 + k0 + lc + 4];
            }
#pragma unroll
            for (int mi = 0; mi < 4; mi++)
#pragma unroll
                for (int ni = 0; ni < 8; ni++)
                    MMA_TF32(c[mi][ni], a[mi], b[ni]);
        }
    }

#pragma unroll
    for (int mi = 0; mi < 4; mi++) {
        int r0 = wm * 64 + mi * 16 + lr;
#pragma unroll
        for (int ni = 0; ni < 8; ni++) {
            int col = wn * 64 + ni * 8 + 2 * lc;
            float bx = bi[col], by = bi[col + 1];
            *(float2*)(Cp + (size_t)r0 * G4 + col) =
                make_float2(c[mi][ni][0] + bx, c[mi][ni][1] + by);
            *(float2*)(Cp + (size_t)(r0 + 8) * G4 + col) =
                make_float2(c[mi][ni][2] + bx, c[mi][ni][3] + by);
        }
    }
}

// ---------------- prep kernels ----------------
__global__ void prep_wihX(const float* __restrict__ wf, const float* __restrict__ wb) {
    int i = blockIdx.x * 256 + threadIdx.x;
    if (i >= G4 * HID) return;
    int row = i / HID, col = i - row * HID;
    int u = row >> 2, g = row & 3;
    int src = (g * LHU + u) * HID + col;
    g_wihX[0][i] = wf[src]; g_wihX[1][i] = wb[src];
}
__global__ void prep_misc(const float* __restrict__ bf, const float* __restrict__ bb,
                          const float* __restrict__ wf, const float* __restrict__ wb) {
    int i = blockIdx.x * 256 + threadIdx.x;
    if (i < G4) {
        int u = i >> 2, g = i & 3;
        g_biasX[0][i] = bf[g * LHU + u]; g_biasX[1][i] = bb[g * LHU + u];
    }
    if (i < G4 * LHU) {
        int row = i >> 8, k = i & 255;
        int u = row >> 2, g = row & 3;
        int src = (g * LHU + u) * LHU + k;
        g_WhhHi[0][i] = __uint_as_float(tf32r(wf[src]));
        g_WhhHi[1][i] = __uint_as_float(tf32r(wb[src]));
    }
    if (i < 2 * S_TOT * LHU) ((float*)g_hbuf)[i] = 0.f;
    if (i < 16) g_grpbar[i] = 0;
}
__global__ void prep_sent(const float* __restrict__ wsf, const float* __restrict__ wsb) {
    int i = blockIdx.x * 256 + threadIdx.x;
    if (i >= LHU * LHU * 4) return;
    int g = i & 3, u = (i >> 2) & 255, k = i >> 10;
    int src = (g * LHU + u) * LHU + k;
    g_WshhX[0][i] = wsf[src]; g_WshhX[1][i] = wsb[src];
}

// ---------------- persistent tensorized word BiLSTM, v2: no k-split ----------------
// 128 CTAs (dir, mt, nt). 8 warps = (wm 0..1 seq-half of 16) x (wn 0..3 col-quarter of 32).
// Each warp: 16 seq x 32 col, FULL K=256. No reduction phase; epilogue in every warp.
#define WP_SMEM ((8 * 128 * 36 + 2 * 8 * 32 * 36) * 4)   // 221184 (Bs + Ahi + Alo)
__global__ void __launch_bounds__(256) word_persist(const int* __restrict__ mask) {
    extern __shared__ uint32_t smw[];
    uint32_t* Bs  = smw;                  // 8 chunks [128][36]
    uint32_t* Ahi = smw + 8 * 4608;       // 8 chunks [32][36]
    uint32_t* Alo = Ahi + 8 * 1152;

    int cta = blockIdx.x;
    int dir = cta >> 6;
    int mt  = (cta >> 3) & 7;
    int nt  = cta & 7;
    int gid = cta >> 3;
    int tid = threadIdx.x;
    int w   = tid >> 5, lane = tid & 31;
    int wm  = w & 1, wn = w >> 1;         // seq-half, col-quarter
    int lr  = lane >> 2, lc = lane & 3;
    int odd = lc & 1;

    // stage W slice once
    const float* Bsrc = g_WhhHi[dir] + (size_t)(nt * 128) * LHU;
#pragma unroll 4
    for (int i = tid; i < 128 * 64; i += 256) {
        int r = i >> 6, c4 = i & 63;
        float4 v = *(const float4*)(Bsrc + r * 256 + c4 * 4);
        int k = c4 * 4, ch = k >> 5, kin = k & 31;
        *(float4*)(Bs + ch * 4608 + r * 36 + kin) = v;
    }

    // per-thread epilogue constants/state: ONE seq, 4 u-cols
    int seqE = mt * 32 + wm * 16 + lr + (odd ? 8 : 0);
    int uE   = nt * 32 + wn * 8 + (lc >> 1);   // + 2*ni
    uint32_t mb[4];
    {
        uint32_t b0 = 0, b1 = 0, b2 = 0, b3 = 0;
        for (int j = 0; j < 32; j++) {
            b0 |= (uint32_t)(mask[seqE * TLEN + j]      != 0) << j;
            b1 |= (uint32_t)(mask[seqE * TLEN + 32 + j] != 0) << j;
            b2 |= (uint32_t)(mask[seqE * TLEN + 64 + j] != 0) << j;
            b3 |= (uint32_t)(mask[seqE * TLEN + 96 + j] != 0) << j;
        }
        mb[0] = b0; mb[1] = b1; mb[2] = b2; mb[3] = b3;
    }
    float cntE = (float)(__popc(mb[0]) + __popc(mb[1]) + __popc(mb[2]) + __popc(mb[3]));
    float c8[4], pool8[4];
#pragma unroll
    for (int ni = 0; ni < 4; ni++) { c8[ni] = 0.f; pool8[ni] = 0.f; }

    const float* Gd = g_G[dir];
    float4 Gpre[4];
    {
        int t0 = dir ? (TLEN - 1) : 0;
#pragma unroll
        for (int ni = 0; ni < 4; ni++)
            Gpre[ni] = *(const float4*)(Gd + ((size_t)seqE * TLEN + t0) * G4 + 4 * (uE + 2 * ni));
    }
    __syncthreads();

    for (int step = 0; step < TLEN; step++) {
        int t = dir ? (TLEN - 1 - step) : step;
        const float* hcur  = g_hbuf[step & 1][dir];
        float*       hnext = g_hbuf[(step + 1) & 1][dir];

        // stage A: h rows mt*32..+32, all 256 k, hi/lo split
#pragma unroll
        for (int it = 0; it < 8; it++) {
            int i = tid + it * 256;
            int r = i >> 6, c4 = i & 63;
            float4 v = *(const float4*)(hcur + (size_t)(mt * 32 + r) * LHU + c4 * 4);
            int k = c4 * 4, ch = k >> 5, kin = k & 31;
            uint32_t hx = tf32r(v.x), hy = tf32r(v.y), hz = tf32r(v.z), hw = tf32r(v.w);
            uint32_t* dh = Ahi + ch * 1152 + r * 36 + kin;
            dh[0] = hx; dh[1] = hy; dh[2] = hz; dh[3] = hw;
            uint32_t* dl = Alo + ch * 1152 + r * 36 + kin;
            dl[0] = tf32r(v.x - __uint_as_float(hx));
            dl[1] = tf32r(v.y - __uint_as_float(hy));
            dl[2] = tf32r(v.z - __uint_as_float(hz));
            dl[3] = tf32r(v.w - __uint_as_float(hw));
        }
        __syncthreads();

        float acc[4][4];
#pragma unroll
        for (int ni = 0; ni < 4; ni++)
#pragma unroll
            for (int j = 0; j < 4; j++) acc[ni][j] = 0.f;

#pragma unroll
        for (int ch = 0; ch < 8; ch++) {
            const uint32_t* Ah = Ahi + ch * 1152 + wm * 16 * 36;
            const uint32_t* Al = Alo + ch * 1152 + wm * 16 * 36;
            const uint32_t* Bc = Bs  + ch * 4608 + wn * 32 * 36;
#pragma unroll
            for (int kk = 0; kk < 4; kk++) {
                int k0 = kk * 8;
                uint32_t aH[4], aL[4];
                aH[0] = Ah[lr * 36 + k0 + lc];
                aH[1] = Ah[(lr + 8) * 36 + k0 + lc];
                aH[2] = Ah[lr * 36 + k0 + lc + 4];
                aH[3] = Ah[(lr + 8) * 36 + k0 + lc + 4];
                aL[0] = Al[lr * 36 + k0 + lc];
                aL[1] = Al[(lr + 8) * 36 + k0 + lc];
                aL[2] = Al[lr * 36 + k0 + lc + 4];
                aL[3] = Al[(lr + 8) * 36 + k0 + lc + 4];
                uint32_t b[4][2];
#pragma unroll
                for (int ni = 0; ni < 4; ni++) {
                    int n = ni * 8 + lr;
                    b[ni][0] = Bc[n * 36 + k0 + lc];
                    b[ni][1] = Bc[n * 36 + k0 + lc + 4];
                }
#pragma unroll
                for (int ni = 0; ni < 4; ni++) {
                    MMA_TF32(acc[ni], aH, b[ni]);
                    MMA_TF32(acc[ni], aL, b[ni]);
                }
            }
        }

        // epilogue: every warp, every thread — one seq, 4 u-cols
        {
            float mk = (float)((mb[t >> 5] >> (t & 31)) & 1u);
#pragma unroll
            for (int ni = 0; ni < 4; ni++) {
                float x0 = acc[ni][0], x1 = acc[ni][1];
                float x2 = acc[ni][2], x3 = acc[ni][3];
                float r0 = __shfl_xor_sync(0xffffffff, x0, 1);
                float r1 = __shfl_xor_sync(0xffffffff, x1, 1);
                float r2 = __shfl_xor_sync(0xffffffff, x2, 1);
                float r3 = __shfl_xor_sync(0xffffffff, x3, 1);
                float gi, gf, gg, go;
                if (!odd) { gi = x0; gf = x1; gg = r0; go = r1; }
                else      { gi = r2; gf = r3; gg = x2; go = x3; }
                float4 Gv = Gpre[ni];
                float iv = sigf(gi + Gv.x);
                float fv = sigf(gf + Gv.y);
                float gv = tanh_(gg + Gv.z);
                float ov = sigf(go + Gv.w);
                float cc2 = fv * c8[ni] + iv * gv;
                c8[ni] = cc2;
                float hn = ov * tanh_(cc2);
                pool8[ni] += mk * hn;
                hnext[seqE * LHU + uE + 2 * ni] = hn;
            }
            if (step + 1 < TLEN) {
                int t2 = dir ? (TLEN - 2 - step) : (step + 1);
#pragma unroll
                for (int ni = 0; ni < 4; ni++)
                    Gpre[ni] = *(const float4*)(Gd + ((size_t)seqE * TLEN + t2) * G4 + 4 * (uE + 2 * ni));
            }
        }

        if (step != TLEN - 1) {
            __threadfence();
            __syncthreads();
            if (tid == 0) {
                atomicAdd(&g_grpbar[gid], 1);
                int target = (step + 1) * 8;
                while (*((volatile int*)&g_grpbar[gid]) < target) { }
            }
            __syncthreads();
            __threadfence();
        }
    }

    // masked mean -> emb
#pragma unroll
    for (int ni = 0; ni < 4; ni++)
        g_emb[seqE * (2 * LHU) + dir * LHU + uE + 2 * ni] =
            (cntE > 0.f) ? (pool8[ni] / cntE) : 0.f;
}

// ---------------- sentence-level LSTM (fwd scan + bwd single step) ----------------
__device__ __forceinline__ u64 pack2(float lo, float hi) {
    u64 r;
    asm("mov.b64 %0, {%1, %2};" : "=l"(r) : "r"(__float_as_uint(lo)), "r"(__float_as_uint(hi)));
    return r;
}
__device__ __forceinline__ u64 dup2(float x) { return pack2(x, x); }
__device__ __forceinline__ void fma2(u64& a, u64 b, u64 c) {
    asm("fma.rn.f32x2 %0, %1, %2, %0;" : "+l"(a) : "l"(b), "l"(c));
}
__device__ __forceinline__ float2 unpack2(u64 v) {
    unsigned lo, hi;
    asm("mov.b64 {%0, %1}, %2;" : "=r"(lo), "=r"(hi) : "l"(v));
    return make_float2(__uint_as_float(lo), __uint_as_float(hi));
}
__global__ void __launch_bounds__(256) sent_lstm() {
    int b = blockIdx.x, u = threadIdx.x;
    __shared__ float h[LHU];
    h[u] = 0.f;
    float c = 0.f;
    __syncthreads();

    const ulonglong2* W2 = (const ulonglong2*)g_WshhX[0];
    for (int t = 0; t < NSENT; t++) {
        const float* gp = g_Gs[0] + (size_t)(b * NSENT + t) * G4;
        u64 aif = pack2(gp[u],           gp[LHU + u]);
        u64 ago = pack2(gp[2 * LHU + u], gp[3 * LHU + u]);
#pragma unroll 8
        for (int k = 0; k < LHU; k++) {
            ulonglong2 w = W2[k * LHU + u];
            u64 hd = dup2(h[k]);
            fma2(aif, w.x, hd);
            fma2(ago, w.y, hd);
        }
        float2 v1 = unpack2(aif), v2 = unpack2(ago);
        float cc = sigf(v1.y) * c + sigf(v1.x) * tanh_(v2.x);
        c = cc;
        float hn = sigf(v2.y) * tanh_(cc);
        __syncthreads();
        h[u] = hn;
        __syncthreads();
    }
    g_final[b * 2 * LHU + u] = h[u];

    const float* gp = g_Gs[1] + (size_t)(b * NSENT + NSENT - 1) * G4;
    float cc = sigf(gp[u]) * tanh_(gp[2 * LHU + u]);
    g_final[b * 2 * LHU + LHU + u] = sigf(gp[3 * LHU + u]) * tanh_(cc);
}

// ---------------- classifier ----------------
__global__ void classify(const float* __restrict__ cw, const float* __restrict__ cb,
                         float* __restrict__ out) {
    int tid = threadIdx.x;
    if (tid >= 32) return;
    int b = tid >> 2, cc = tid & 3;
    float s = cb[cc];
    for (int k = 0; k < 2 * LHU; k++)
        s += g_final[b * 2 * LHU + k] * cw[cc * 2 * LHU + k];
    out[b * 4 + cc] = s;
}

// ---------------- launch ----------------
extern "C" void kernel_launch(void* const* d_in, const int* in_sizes, int n_in,
                              void* d_out, int out_size) {
    const float* hidden  = (const float*)d_in[0];
    const int*   amask   = (const int*)  d_in[1];
    const float* wl_ih_f = (const float*)d_in[2];
    const float* wl_hh_f = (const float*)d_in[3];
    const float* wl_b_f  = (const float*)d_in[4];
    const float* wl_ih_b = (const float*)d_in[5];
    const float* wl_hh_b = (const float*)d_in[6];
    const float* wl_b_b  = (const float*)d_in[7];
    const float* ws_ih_f = (const float*)d_in[8];
    const float* ws_hh_f = (const float*)d_in[9];
    const float* ws_b_f  = (const float*)d_in[10];
    const float* ws_ih_b = (const float*)d_in[11];
    const float* ws_hh_b = (const float*)d_in[12];
    const float* ws_b_b  = (const float*)d_in[13];
    const float* cls_w   = (const float*)d_in[14];
    const float* cls_b   = (const float*)d_in[15];
    float* out = (float*)d_out;

    float *G0, *Gs0, *emb, *wihX0, *biasX0;
    cudaGetSymbolAddress((void**)&G0,     g_G);
    cudaGetSymbolAddress((void**)&Gs0,    g_Gs);
    cudaGetSymbolAddress((void**)&emb,    g_emb);
    cudaGetSymbolAddress((void**)&wihX0,  g_wihX);
    cudaGetSymbolAddress((void**)&biasX0, g_biasX);
    float* G1     = G0    + (size_t)S_TOT * TLEN * G4;
    float* Gs1    = Gs0   + (size_t)S_TOT * G4;
    float* wihX1  = wihX0 + (size_t)G4 * HID;
    float* biasX1 = biasX0 + G4;

    cudaFuncSetAttribute(mma_gemm,     cudaFuncAttributeMaxDynamicSharedMemorySize, GEMM_SMEM);
    cudaFuncSetAttribute(word_persist, cudaFuncAttributeMaxDynamicSharedMemorySize, WP_SMEM);

    // #1, #2: prep
    prep_wihX<<<(G4 * HID + 255) / 256, 256>>>(wl_ih_f, wl_ih_b);
    prep_misc<<<(G4 * LHU + 255) / 256, 256>>>(wl_b_f, wl_b_b, wl_hh_f, wl_hh_b);
    // #3: word pre-gates (interleaved cols)
    mma_gemm<<<dim3(8, (S_TOT * TLEN) / 128), 256, GEMM_SMEM>>>(
        hidden, wihX0, wihX1, biasX0, biasX1, G0, G1, HID);
    // #4: persistent tensorized word BiLSTM (profiled)
    word_persist<<<NCTA, 256, WP_SMEM>>>(amask);
    // #5-#8
    prep_sent<<<(LHU * LHU * 4 + 255) / 256, 256>>>(ws_hh_f, ws_hh_b);
    mma_gemm<<<dim3(8, S_TOT / 128), 256, GEMM_SMEM>>>(
        emb, ws_ih_f, ws_ih_b, ws_b_f, ws_b_b, Gs0, Gs1, 2 * LHU);
    sent_lstm<<<BATCH, 256>>>();
    classify<<<1, 32>>>(cls_w, cls_b, out);
}

// round 16
// speedup vs baseline: 1.8366x; 1.0707x over previous
#include <cuda_runtime.h>
#include <cuda_bf16.h>
#include <cstdint>

#define TLEN   128
#define HID    768
#define LHU    256
#define G4     1024
#define S_TOT  256
#define BATCH  8
#define NSENT  32
#define NCTA   128

typedef unsigned long long u64;

// ---------------- device scratch ----------------
__device__ float g_G    [2][(size_t)S_TOT * TLEN * G4];  // word pre-gates, gate-interleaved cols (4u+g)
__device__ float g_emb  [S_TOT * 2 * LHU];
__device__ float g_WshhX[2][LHU * LHU * 4];
__device__ float g_Gs   [2][S_TOT * G4];
__device__ float g_final[BATCH * 2 * LHU];
__device__ float g_wihX [2][G4 * HID];                   // word Wih rows permuted to 4u+g
__device__ float g_biasX[2][G4];
__device__ float g_WhhHi[2][G4 * LHU];                   // word Whh rows 4u+g, tf32-rounded
__device__ float g_hbuf [2][2][S_TOT * LHU];             // [parity][dir][seq*256+u]
__device__ int   g_grpbar[16];                           // per-(dir,mt) group barriers

// ---------------- helpers ----------------
__device__ __forceinline__ float sigf(float x) { return 1.f / (1.f + __expf(-x)); }
__device__ __forceinline__ float tanh_(float x) {
    float e = __expf(-2.f * fabsf(x));
    float r = (1.f - e) / (1.f + e);
    return copysignf(r, x);
}
__device__ __forceinline__ uint32_t tf32r(float f) {
    uint32_t o;
    asm("cvt.rna.tf32.f32 %0, %1;" : "=r"(o) : "f"(f));
    return o;
}
#define MMA_TF32(cc, a, b)                                              \
    asm volatile(                                                       \
        "mma.sync.aligned.m16n8k8.row.col.f32.tf32.tf32.f32 "           \
        "{%0,%1,%2,%3}, {%4,%5,%6,%7}, {%8,%9}, {%0,%1,%2,%3};"         \
        : "+f"((cc)[0]), "+f"((cc)[1]), "+f"((cc)[2]), "+f"((cc)[3])    \
        : "r"((a)[0]), "r"((a)[1]), "r"((a)[2]), "r"((a)[3]),           \
          "r"((b)[0]), "r"((b)[1]))

// ---------------- tf32 mma.sync GEMM, CTA 128x256, 8 warps (2M x 4N), warp 64x64 (R13 form) ----------------
#define GEMM_SMEM ((128 * 36 + 256 * 36) * 4)
__global__ void __launch_bounds__(256) mma_gemm(
    const float* __restrict__ A,
    const float* __restrict__ B0, const float* __restrict__ B1,
    const float* __restrict__ bias0, const float* __restrict__ bias1,
    float* __restrict__ C0, float* __restrict__ C1,
    int K)
{
    extern __shared__ uint32_t smq[];
    uint32_t* As = smq;
    uint32_t* Bs = smq + 128 * 36;

    int dir = blockIdx.x >> 2;
    int nt  = blockIdx.x & 3;
    int mt  = blockIdx.y;
    const float* Ap = A + (size_t)mt * 128 * K;
    const float* Bp = (dir ? B1 : B0) + (size_t)nt * 256 * K;
    const float* bi = (dir ? bias1 : bias0) + nt * 256;
    float* Cp = (dir ? C1 : C0) + (size_t)mt * 128 * G4 + nt * 256;

    int tid = threadIdx.x;
    int warp = tid >> 5, lane = tid & 31;
    int wm = warp & 1, wn = warp >> 1;
    int lr = lane >> 2, lc = lane & 3;

    float c[4][8][4];
#pragma unroll
    for (int mi = 0; mi < 4; mi++)
#pragma unroll
        for (int ni = 0; ni < 8; ni++)
#pragma unroll
            for (int j = 0; j < 4; j++) c[mi][ni][j] = 0.f;

    int nkt = K >> 5;
    for (int kt = 0; kt < nkt; kt++) {
        __syncthreads();
#pragma unroll
        for (int it = 0; it < 4; it++) {
            int i = tid + it * 256;
            int row = i >> 3, c4 = i & 7;
            float4 v = *(const float4*)(Ap + (size_t)row * K + kt * 32 + c4 * 4);
            uint32_t* d = As + row * 36 + c4 * 4;
            d[0] = tf32r(v.x); d[1] = tf32r(v.y); d[2] = tf32r(v.z); d[3] = tf32r(v.w);
        }
#pragma unroll
        for (int it = 0; it < 8; it++) {
            int i = tid + it * 256;
            int row = i >> 3, c4 = i & 7;
            float4 v = *(const float4*)(Bp + (size_t)row * K + kt * 32 + c4 * 4);
            uint32_t* d = Bs + row * 36 + c4 * 4;
            d[0] = tf32r(v.x); d[1] = tf32r(v.y); d[2] = tf32r(v.z); d[3] = tf32r(v.w);
        }
        __syncthreads();

#pragma unroll
        for (int kk = 0; kk < 4; kk++) {
            int k0 = kk * 8;
            uint32_t a[4][4];
#pragma unroll
            for (int mi = 0; mi < 4; mi++) {
                int r = wm * 64 + mi * 16 + lr;
                a[mi][0] = As[r * 36 + k0 + lc];
                a[mi][1] = As[(r + 8) * 36 + k0 + lc];
                a[mi][2] = As[r * 36 + k0 + lc + 4];
                a[mi][3] = As[(r + 8) * 36 + k0 + lc + 4];
            }
            uint32_t b[8][2];
#pragma unroll
            for (int ni = 0; ni < 8; ni++) {
                int n = wn * 64 + ni * 8 + lr;
                b[ni][0] = Bs[n * 36 + k0 + lc];
                b[ni][1] = Bs[n * 36 + k0 + lc + 4];
            }
#pragma unroll
            for (int mi = 0; mi < 4; mi++)
#pragma unroll
                for (int ni = 0; ni < 8; ni++)
                    MMA_TF32(c[mi][ni], a[mi], b[ni]);
        }
    }

#pragma unroll
    for (int mi = 0; mi < 4; mi++) {
        int r0 = wm * 64 + mi * 16 + lr;
#pragma unroll
        for (int ni = 0; ni < 8; ni++) {
            int col = wn * 64 + ni * 8 + 2 * lc;
            float bx = bi[col], by = bi[col + 1];
            *(float2*)(Cp + (size_t)r0 * G4 + col) =
                make_float2(c[mi][ni][0] + bx, c[mi][ni][1] + by);
            *(float2*)(Cp + (size_t)(r0 + 8) * G4 + col) =
                make_float2(c[mi][ni][2] + bx, c[mi][ni][3] + by);
        }
    }
}

// ---------------- prep kernels ----------------
__global__ void prep_wihX(const float* __restrict__ wf, const float* __restrict__ wb) {
    int i = blockIdx.x * 256 + threadIdx.x;
    if (i >= G4 * HID) return;
    int row = i / HID, col = i - row * HID;
    int u = row >> 2, g = row & 3;
    int src = (g * LHU + u) * HID + col;
    g_wihX[0][i] = wf[src]; g_wihX[1][i] = wb[src];
}
__global__ void prep_misc(const float* __restrict__ bf, const float* __restrict__ bb,
                          const float* __restrict__ wf, const float* __restrict__ wb) {
    int i = blockIdx.x * 256 + threadIdx.x;
    if (i < G4) {
        int u = i >> 2, g = i & 3;
        g_biasX[0][i] = bf[g * LHU + u]; g_biasX[1][i] = bb[g * LHU + u];
    }
    if (i < G4 * LHU) {
        int row = i >> 8, k = i & 255;
        int u = row >> 2, g = row & 3;
        int src = (g * LHU + u) * LHU + k;
        g_WhhHi[0][i] = __uint_as_float(tf32r(wf[src]));
        g_WhhHi[1][i] = __uint_as_float(tf32r(wb[src]));
    }
    if (i < 2 * S_TOT * LHU) ((float*)g_hbuf)[i] = 0.f;
    if (i < 16) g_grpbar[i] = 0;
}
__global__ void prep_sent(const float* __restrict__ wsf, const float* __restrict__ wsb) {
    int i = blockIdx.x * 256 + threadIdx.x;
    if (i >= LHU * LHU * 4) return;
    int g = i & 3, u = (i >> 2) & 255, k = i >> 10;
    int src = (g * LHU + u) * LHU + k;
    g_WshhX[0][i] = wsf[src]; g_WshhX[1][i] = wsb[src];
}

// ---------------- persistent tensorized word BiLSTM, v3: no k-split, single-tf32 h ----------------
// 128 CTAs (dir, mt, nt). 8 warps = (wm seq-half of 16) x (wn col-quarter of 32).
// Each warp: 16 seq x 32 col, FULL K=256, single tf32 A (no lo residual).
#define WP_SMEM ((8 * 128 * 36 + 8 * 32 * 36) * 4)   // 165888 (Bs + Ahi)
__global__ void __launch_bounds__(256) word_persist(const int* __restrict__ mask) {
    extern __shared__ uint32_t smw[];
    uint32_t* Bs  = smw;                  // 8 chunks [128][36]
    uint32_t* Ahi = smw + 8 * 4608;       // 8 chunks [32][36]

    int cta = blockIdx.x;
    int dir = cta >> 6;
    int mt  = (cta >> 3) & 7;
    int nt  = cta & 7;
    int gid = cta >> 3;
    int tid = threadIdx.x;
    int w   = tid >> 5, lane = tid & 31;
    int wm  = w & 1, wn = w >> 1;
    int lr  = lane >> 2, lc = lane & 3;
    int odd = lc & 1;

    // stage W slice once
    const float* Bsrc = g_WhhHi[dir] + (size_t)(nt * 128) * LHU;
#pragma unroll 4
    for (int i = tid; i < 128 * 64; i += 256) {
        int r = i >> 6, c4 = i & 63;
        float4 v = *(const float4*)(Bsrc + r * 256 + c4 * 4);
        int k = c4 * 4, ch = k >> 5, kin = k & 31;
        *(float4*)(Bs + ch * 4608 + r * 36 + kin) = v;
    }

    // per-thread epilogue constants/state: ONE seq, 4 u-cols
    int seqE = mt * 32 + wm * 16 + lr + (odd ? 8 : 0);
    int uE   = nt * 32 + wn * 8 + (lc >> 1);
    uint32_t mb[4];
    {
        uint32_t b0 = 0, b1 = 0, b2 = 0, b3 = 0;
        for (int j = 0; j < 32; j++) {
            b0 |= (uint32_t)(mask[seqE * TLEN + j]      != 0) << j;
            b1 |= (uint32_t)(mask[seqE * TLEN + 32 + j] != 0) << j;
            b2 |= (uint32_t)(mask[seqE * TLEN + 64 + j] != 0) << j;
            b3 |= (uint32_t)(mask[seqE * TLEN + 96 + j] != 0) << j;
        }
        mb[0] = b0; mb[1] = b1; mb[2] = b2; mb[3] = b3;
    }
    float cntE = (float)(__popc(mb[0]) + __popc(mb[1]) + __popc(mb[2]) + __popc(mb[3]));
    float c8[4], pool8[4];
#pragma unroll
    for (int ni = 0; ni < 4; ni++) { c8[ni] = 0.f; pool8[ni] = 0.f; }

    const float* Gd = g_G[dir];
    float4 Gpre[4];
    {
        int t0 = dir ? (TLEN - 1) : 0;
#pragma unroll
        for (int ni = 0; ni < 4; ni++)
            Gpre[ni] = *(const float4*)(Gd + ((size_t)seqE * TLEN + t0) * G4 + 4 * (uE + 2 * ni));
    }
    __syncthreads();

    for (int step = 0; step < TLEN; step++) {
        int t = dir ? (TLEN - 1 - step) : step;
        const float* hcur  = g_hbuf[step & 1][dir];
        float*       hnext = g_hbuf[(step + 1) & 1][dir];

        // stage A: h rows mt*32..+32, all 256 k, single tf32
#pragma unroll
        for (int it = 0; it < 8; it++) {
            int i = tid + it * 256;
            int r = i >> 6, c4 = i & 63;
            float4 v = *(const float4*)(hcur + (size_t)(mt * 32 + r) * LHU + c4 * 4);
            int k = c4 * 4, ch = k >> 5, kin = k & 31;
            uint32_t* dh = Ahi + ch * 1152 + r * 36 + kin;
            dh[0] = tf32r(v.x); dh[1] = tf32r(v.y);
            dh[2] = tf32r(v.z); dh[3] = tf32r(v.w);
        }
        __syncthreads();

        float acc[4][4];
#pragma unroll
        for (int ni = 0; ni < 4; ni++)
#pragma unroll
            for (int j = 0; j < 4; j++) acc[ni][j] = 0.f;

#pragma unroll
        for (int ch = 0; ch < 8; ch++) {
            const uint32_t* Ah = Ahi + ch * 1152 + wm * 16 * 36;
            const uint32_t* Bc = Bs  + ch * 4608 + wn * 32 * 36;
#pragma unroll
            for (int kk = 0; kk < 4; kk++) {
                int k0 = kk * 8;
                uint32_t aH[4];
                aH[0] = Ah[lr * 36 + k0 + lc];
                aH[1] = Ah[(lr + 8) * 36 + k0 + lc];
                aH[2] = Ah[lr * 36 + k0 + lc + 4];
                aH[3] = Ah[(lr + 8) * 36 + k0 + lc + 4];
                uint32_t b[4][2];
#pragma unroll
                for (int ni = 0; ni < 4; ni++) {
                    int n = ni * 8 + lr;
                    b[ni][0] = Bc[n * 36 + k0 + lc];
                    b[ni][1] = Bc[n * 36 + k0 + lc + 4];
                }
#pragma unroll
                for (int ni = 0; ni < 4; ni++)
                    MMA_TF32(acc[ni], aH, b[ni]);
            }
        }

        // epilogue: every warp, every thread — one seq, 4 u-cols
        {
            float mk = (float)((mb[t >> 5] >> (t & 31)) & 1u);
#pragma unroll
            for (int ni = 0; ni < 4; ni++) {
                float x0 = acc[ni][0], x1 = acc[ni][1];
                float x2 = acc[ni][2], x3 = acc[ni][3];
                float r0 = __shfl_xor_sync(0xffffffff, x0, 1);
                float r1 = __shfl_xor_sync(0xffffffff, x1, 1);
                float r2 = __shfl_xor_sync(0xffffffff, x2, 1);
                float r3 = __shfl_xor_sync(0xffffffff, x3, 1);
                float gi, gf, gg, go;
                if (!odd) { gi = x0; gf = x1; gg = r0; go = r1; }
                else      { gi = r2; gf = r3; gg = x2; go = x3; }
                float4 Gv = Gpre[ni];
                float iv = sigf(gi + Gv.x);
                float fv = sigf(gf + Gv.y);
                float gv = tanh_(gg + Gv.z);
                float ov = sigf(go + Gv.w);
                float cc2 = fv * c8[ni] + iv * gv;
                c8[ni] = cc2;
                float hn = ov * tanh_(cc2);
                pool8[ni] += mk * hn;
                hnext[seqE * LHU + uE + 2 * ni] = hn;
            }
            if (step + 1 < TLEN) {
                int t2 = dir ? (TLEN - 2 - step) : (step + 1);
#pragma unroll
                for (int ni = 0; ni < 4; ni++)
                    Gpre[ni] = *(const float4*)(Gd + ((size_t)seqE * TLEN + t2) * G4 + 4 * (uE + 2 * ni));
            }
        }

        if (step != TLEN - 1) {
            __threadfence();
            __syncthreads();
            if (tid == 0) {
                atomicAdd(&g_grpbar[gid], 1);
                int target = (step + 1) * 8;
                while (*((volatile int*)&g_grpbar[gid]) < target) { }
            }
            __syncthreads();
            __threadfence();
        }
    }

    // masked mean -> emb
#pragma unroll
    for (int ni = 0; ni < 4; ni++)
        g_emb[seqE * (2 * LHU) + dir * LHU + uE + 2 * ni] =
            (cntE > 0.f) ? (pool8[ni] / cntE) : 0.f;
}

// ---------------- sentence-level LSTM (fwd scan + bwd single step) ----------------
__device__ __forceinline__ u64 pack2(float lo, float hi) {
    u64 r;
    asm("mov.b64 %0, {%1, %2};" : "=l"(r) : "r"(__float_as_uint(lo)), "r"(__float_as_uint(hi)));
    return r;
}
__device__ __forceinline__ u64 dup2(float x) { return pack2(x, x); }
__device__ __forceinline__ void fma2(u64& a, u64 b, u64 c) {
    asm("fma.rn.f32x2 %0, %1, %2, %0;" : "+l"(a) : "l"(b), "l"(c));
}
__device__ __forceinline__ float2 unpack2(u64 v) {
    unsigned lo, hi;
    asm("mov.b64 {%0, %1}, %2;" : "=r"(lo), "=r"(hi) : "l"(v));
    return make_float2(__uint_as_float(lo), __uint_as_float(hi));
}
__global__ void __launch_bounds__(256) sent_lstm() {
    int b = blockIdx.x, u = threadIdx.x;
    __shared__ float h[LHU];
    h[u] = 0.f;
    float c = 0.f;
    __syncthreads();

    const ulonglong2* W2 = (const ulonglong2*)g_WshhX[0];
    for (int t = 0; t < NSENT; t++) {
        const float* gp = g_Gs[0] + (size_t)(b * NSENT + t) * G4;
        u64 aif = pack2(gp[u],           gp[LHU + u]);
        u64 ago = pack2(gp[2 * LHU + u], gp[3 * LHU + u]);
#pragma unroll 8
        for (int k = 0; k < LHU; k++) {
            ulonglong2 w = W2[k * LHU + u];
            u64 hd = dup2(h[k]);
            fma2(aif, w.x, hd);
            fma2(ago, w.y, hd);
        }
        float2 v1 = unpack2(aif), v2 = unpack2(ago);
        float cc = sigf(v1.y) * c + sigf(v1.x) * tanh_(v2.x);
        c = cc;
        float hn = sigf(v2.y) * tanh_(cc);
        __syncthreads();
        h[u] = hn;
        __syncthreads();
    }
    g_final[b * 2 * LHU + u] = h[u];

    const float* gp = g_Gs[1] + (size_t)(b * NSENT + NSENT - 1) * G4;
    float cc = sigf(gp[u]) * tanh_(gp[2 * LHU + u]);
    g_final[b * 2 * LHU + LHU + u] = sigf(gp[3 * LHU + u]) * tanh_(cc);
}

// ---------------- classifier ----------------
__global__ void classify(const float* __restrict__ cw, const float* __restrict__ cb,
                         float* __restrict__ out) {
    int tid = threadIdx.x;
    if (tid >= 32) return;
    int b = tid >> 2, cc = tid & 3;
    float s = cb[cc];
    for (int k = 0; k < 2 * LHU; k++)
        s += g_final[b * 2 * LHU + k] * cw[cc * 2 * LHU + k];
    out[b * 4 + cc] = s;
}

// ---------------- launch ----------------
extern "C" void kernel_launch(void* const* d_in, const int* in_sizes, int n_in,
                              void* d_out, int out_size) {
    const float* hidden  = (const float*)d_in[0];
    const int*   amask   = (const int*)  d_in[1];
    const float* wl_ih_f = (const float*)d_in[2];
    const float* wl_hh_f = (const float*)d_in[3];
    const float* wl_b_f  = (const float*)d_in[4];
    const float* wl_ih_b = (const float*)d_in[5];
    const float* wl_hh_b = (const float*)d_in[6];
    const float* wl_b_b  = (const float*)d_in[7];
    const float* ws_ih_f = (const float*)d_in[8];
    const float* ws_hh_f = (const float*)d_in[9];
    const float* ws_b_f  = (const float*)d_in[10];
    const float* ws_ih_b = (const float*)d_in[11];
    const float* ws_hh_b = (const float*)d_in[12];
    const float* ws_b_b  = (const float*)d_in[13];
    const float* cls_w   = (const float*)d_in[14];
    const float* cls_b   = (const float*)d_in[15];
    float* out = (float*)d_out;

    float *G0, *Gs0, *emb, *wihX0, *biasX0;
    cudaGetSymbolAddress((void**)&G0,     g_G);
    cudaGetSymbolAddress((void**)&Gs0,    g_Gs);
    cudaGetSymbolAddress((void**)&emb,    g_emb);
    cudaGetSymbolAddress((void**)&wihX0,  g_wihX);
    cudaGetSymbolAddress((void**)&biasX0, g_biasX);
    float* G1     = G0    + (size_t)S_TOT * TLEN * G4;
    float* Gs1    = Gs0   + (size_t)S_TOT * G4;
    float* wihX1  = wihX0 + (size_t)G4 * HID;
    float* biasX1 = biasX0 + G4;

    cudaFuncSetAttribute(mma_gemm,     cudaFuncAttributeMaxDynamicSharedMemorySize, GEMM_SMEM);
    cudaFuncSetAttribute(word_persist, cudaFuncAttributeMaxDynamicSharedMemorySize, WP_SMEM);

    // #1, #2: prep
    prep_wihX<<<(G4 * HID + 255) / 256, 256>>>(wl_ih_f, wl_ih_b);
    prep_misc<<<(G4 * LHU + 255) / 256, 256>>>(wl_b_f, wl_b_b, wl_hh_f, wl_hh_b);
    // #3: word pre-gates (interleaved cols)
    mma_gemm<<<dim3(8, (S_TOT * TLEN) / 128), 256, GEMM_SMEM>>>(
        hidden, wihX0, wihX1, biasX0, biasX1, G0, G1, HID);
    // #4: persistent tensorized word BiLSTM (profiled)
    word_persist<<<NCTA, 256, WP_SMEM>>>(amask);
    // #5-#8
    prep_sent<<<(LHU * LHU * 4 + 255) / 256, 256>>>(ws_hh_f, ws_hh_b);
    mma_gemm<<<dim3(8, S_TOT / 128), 256, GEMM_SMEM>>>(
        emb, ws_ih_f, ws_ih_b, ws_b_f, ws_b_b, Gs0, Gs1, 2 * LHU);
    sent_lstm<<<BATCH, 256>>>();
    classify<<<1, 32>>>(cls_w, cls_b, out);
}